// round 11
// baseline (speedup 1.0000x reference)
#include <cuda_runtime.h>
#include <cuda_fp16.h>
#include <cstdint>

// ToeplitzLinear: D[m,n] = sum_k X[m,k] * vals[4095 - n + k]
// R11 = R10 (barrier-free, A via L2-resident fragment-shuffled LDG.128,
// CTA-lifetime vals window in smem) plus:
//  - cross-iteration prefetch of the first A fragment (kills iter-start stall)
//  - mm-major MMA order (a1 LDGs covered by 32 HMMAs)
//  - Bf rotation: window slides exactly 8 diagonals/iter -> 8 new LDS not 15
//  - __stcs streaming output stores

#define M_DIM 8192
#define N_DIM 4096
#define K_DIM 4096
#define BM 128
#define BN 128
#define BK 64
#define NITER (K_DIM / BK)       // 64
#define THREADS 256

#define VWIN_WORDS 4224

__device__ uint32_t g_xh[(size_t)M_DIM * K_DIM / 2];
__device__ uint32_t g_v2h[8192];   // g_v2h[i] = half2(w[i], w[i+1]), w = fp16(vals)

__device__ __forceinline__ void mma_fp16(float c[4], uint32_t a0, uint32_t a1,
                                         uint32_t a2, uint32_t a3,
                                         uint32_t b0, uint32_t b1) {
    asm volatile(
        "mma.sync.aligned.m16n8k16.row.col.f32.f16.f16.f32 "
        "{%0,%1,%2,%3}, {%4,%5,%6,%7}, {%8,%9}, {%0,%1,%2,%3};"
        : "+f"(c[0]), "+f"(c[1]), "+f"(c[2]), "+f"(c[3])
        : "r"(a0), "r"(a1), "r"(a2), "r"(a3), "r"(b0), "r"(b1));
}

// ---- pre-pass: X -> fp16 fragment-shuffled; block(0,0) also builds g_v2h ----
__global__ void __launch_bounds__(128) cvt_x_kernel(const float* __restrict__ x,
                                                    const float* __restrict__ v) {
    __shared__ float sm[16 * 128];
    const int tid = threadIdx.x;
    const int rb = blockIdx.y;
    const int c0 = blockIdx.x * 128;

    if (blockIdx.x == 0 && blockIdx.y == 0) {
        for (int i = tid; i < 8192; i += 128) {
            float a = (i < 8191) ? v[i] : 0.0f;
            float b = (i + 1 < 8191) ? v[i + 1] : 0.0f;
            __half2 h = __floats2half2_rn(a, b);
            g_v2h[i] = *reinterpret_cast<uint32_t*>(&h);
        }
    }
#pragma unroll
    for (int i = 0; i < 4; i++) {
        const int f = tid + 128 * i;
        const int r = f >> 5;
        const int cq = f & 31;
        float4 vv = *reinterpret_cast<const float4*>(
            x + (size_t)(rb * 16 + r) * K_DIM + c0 + cq * 4);
        float* s = sm + r * 128 + cq * 4;
        s[0] = vv.x; s[1] = vv.y; s[2] = vv.z; s[3] = vv.w;
    }
    __syncthreads();
#pragma unroll
    for (int i = 0; i < 4; i++) {
        const int p = tid + 128 * i;
        const int cbL = p >> 6;
        const int pw = p & 63;
        const int widx = pw * 2;
        const int lane = widx >> 2;
        const int j = widx & 3;
        const int g = lane >> 2;
        const int tig = lane & 3;
        const int k = cbL * 16 + 2 * tig + (j >> 1) * 8;
        __half2 lo = __floats2half2_rn(sm[g * 128 + k], sm[g * 128 + k + 1]);
        __half2 hi = __floats2half2_rn(sm[(g + 8) * 128 + k], sm[(g + 8) * 128 + k + 1]);
        uint2 u;
        u.x = *reinterpret_cast<uint32_t*>(&lo);
        u.y = *reinterpret_cast<uint32_t*>(&hi);
        *reinterpret_cast<uint2*>(
            g_xh + ((size_t)rb * 256 + (c0 >> 4) + cbL) * 128 + widx) = u;
    }
}

__global__ void __launch_bounds__(THREADS, 2)
toeplitz_mma_kernel(float* __restrict__ out) {
    __shared__ uint32_t sv[VWIN_WORDS];

    const int tid = threadIdx.x;
    const int wid = tid >> 5;
    const int lane = tid & 31;
    const int g = lane >> 2;
    const int tig = lane & 3;
    const int warpM = wid & 3;
    const int warpN = wid >> 2;

    const int n0 = blockIdx.x * BN;
    const int m0 = blockIdx.y * BM;
    const int vbase = 3968 - n0;

    {
        const uint4* src = reinterpret_cast<const uint4*>(g_v2h + vbase);
        uint4* dst = reinterpret_cast<uint4*>(sv);
        for (int i = tid; i < VWIN_WORDS / 4; i += THREADS) dst[i] = src[i];
    }

    float acc[2][8][4];
#pragma unroll
    for (int mm = 0; mm < 2; mm++)
#pragma unroll
        for (int nn = 0; nn < 8; nn++)
#pragma unroll
            for (int r = 0; r < 4; r++) acc[mm][nn][r] = 0.0f;

    __syncthreads();   // only barrier before epilogue

    const int Q = 2 * tig - g + 71 - warpN * 64;   // [0,77]

    const uint4* ap0 = reinterpret_cast<const uint4*>(
        g_xh + ((size_t)((m0 >> 4) + warpM * 2 + 0) * 256) * 128) + lane;
    const uint4* ap1 = reinterpret_cast<const uint4*>(
        g_xh + ((size_t)((m0 >> 4) + warpM * 2 + 1) * 256) * 128) + lane;

    // initial B fragments for t=0 (15 diagonals)
    uint32_t Bf[15];
#pragma unroll
    for (int e = 0; e < 15; e++) Bf[e] = sv[Q + 8 * e];

    // prefetch first A fragment of t=0
    uint4 pa0 = __ldg(ap0);

#pragma unroll 1
    for (int t = 0; t < NITER; t++) {
        // A fragments: first a0 chunk comes from the prefetch register
        uint4 a0[4], a1[4];
        a0[0] = pa0;
#pragma unroll
        for (int ks = 1; ks < 4; ks++)
            a0[ks] = __ldg(ap0 + (size_t)(4 * t + ks) * 32);
#pragma unroll
        for (int ks = 0; ks < 4; ks++)
            a1[ks] = __ldg(ap1 + (size_t)(4 * t + ks) * 32);
        if (t + 1 < NITER) pa0 = __ldg(ap0 + (size_t)(4 * t + 4) * 32);

        // mm-major: all acc[0] MMAs first (covers a1 load latency)
#pragma unroll
        for (int ks = 0; ks < 4; ks++)
#pragma unroll
            for (int nn = 0; nn < 8; nn++) {
                const int e = 2 * ks - nn + 7;
                mma_fp16(acc[0][nn], a0[ks].x, a0[ks].y, a0[ks].z, a0[ks].w,
                         Bf[e], Bf[e + 1]);
            }
#pragma unroll
        for (int ks = 0; ks < 4; ks++)
#pragma unroll
            for (int nn = 0; nn < 8; nn++) {
                const int e = 2 * ks - nn + 7;
                mma_fp16(acc[1][nn], a1[ks].x, a1[ks].y, a1[ks].z, a1[ks].w,
                         Bf[e], Bf[e + 1]);
            }

        // rotate B window: slide of 64 pairs == 8 diagonal steps
        if (t + 1 < NITER) {
#pragma unroll
            for (int e = 0; e < 7; e++) Bf[e] = Bf[e + 8];
            const uint32_t* vp = sv + 64 * (t + 1) + Q;
#pragma unroll
            for (int e = 7; e < 15; e++) Bf[e] = vp[8 * e];
        }
    }

    // epilogue: streaming float2 stores (don't evict X scratch from L2)
#pragma unroll
    for (int mm = 0; mm < 2; mm++) {
        const int row = m0 + warpM * 32 + mm * 16 + g;
#pragma unroll
        for (int nn = 0; nn < 8; nn++) {
            const int col = n0 + warpN * 64 + nn * 8 + tig * 2;
            __stcs(reinterpret_cast<float2*>(out + (size_t)row * N_DIM + col),
                   make_float2(acc[mm][nn][0], acc[mm][nn][1]));
            __stcs(reinterpret_cast<float2*>(out + (size_t)(row + 8) * N_DIM + col),
                   make_float2(acc[mm][nn][2], acc[mm][nn][3]));
        }
    }
}

extern "C" void kernel_launch(void* const* d_in, const int* in_sizes, int n_in,
                              void* d_out, int out_size) {
    const float* x    = (const float*)d_in[0];
    const float* vals = (const float*)d_in[1];
    float* out        = (float*)d_out;

    cvt_x_kernel<<<dim3(K_DIM / 128, M_DIM / 16), 128>>>(x, vals);

    dim3 grid(N_DIM / BN, M_DIM / BM);   // 32 x 64
    toeplitz_mma_kernel<<<grid, THREADS>>>(out);
}

// round 12
// speedup vs baseline: 1.0482x; 1.0482x over previous
#include <cuda_runtime.h>
#include <cuda_fp16.h>
#include <cstdint>

// ToeplitzLinear: D[m,n] = sum_k X[m,k] * vals[4095 - n + k]
// R12 = R10 + warp-private cp.async double-buffered A staging (no barriers,
// no cross-warp coupling). A frags: conflict-free LDS.128 from the warp's own
// smem buffer; refill via per-warp cp.async FIFO. vals pair-window staged in
// smem once per CTA (single __syncthreads).

#define M_DIM 8192
#define N_DIM 4096
#define K_DIM 4096
#define BM 128
#define BN 128
#define BK 64
#define NITER (K_DIM / BK)       // 64
#define THREADS 256

#define VWIN_WORDS 4224
#define WSTAGE_BYTES 4096        // per warp per stage: 2 rb x 4 ks x 32 x 16B
#define SV_OFF 65536             // 8 warps x 2 stages x 4KB
#define SMEM_TOTAL (SV_OFF + VWIN_WORDS * 4)   // 82432

__device__ uint32_t g_xh[(size_t)M_DIM * K_DIM / 2];
__device__ uint32_t g_v2h[8192];   // g_v2h[i] = half2(w[i], w[i+1]), w = fp16(vals)

__device__ __forceinline__ uint32_t smem_u32(const void* p) {
    uint32_t a;
    asm("{ .reg .u64 t; cvta.to.shared.u64 t, %1; cvt.u32.u64 %0, t; }"
        : "=r"(a) : "l"(p));
    return a;
}
__device__ __forceinline__ void cp16(uint32_t saddr, const void* g) {
    asm volatile("cp.async.cg.shared.global [%0], [%1], 16;"
                 :: "r"(saddr), "l"(g) : "memory");
}
__device__ __forceinline__ void cp_commit() {
    asm volatile("cp.async.commit_group;" ::: "memory");
}
template <int N>
__device__ __forceinline__ void cp_wait() {
    asm volatile("cp.async.wait_group %0;" :: "n"(N) : "memory");
}
__device__ __forceinline__ void mma_fp16(float c[4], uint32_t a0, uint32_t a1,
                                         uint32_t a2, uint32_t a3,
                                         uint32_t b0, uint32_t b1) {
    asm volatile(
        "mma.sync.aligned.m16n8k16.row.col.f32.f16.f16.f32 "
        "{%0,%1,%2,%3}, {%4,%5,%6,%7}, {%8,%9}, {%0,%1,%2,%3};"
        : "+f"(c[0]), "+f"(c[1]), "+f"(c[2]), "+f"(c[3])
        : "r"(a0), "r"(a1), "r"(a2), "r"(a3), "r"(b0), "r"(b1));
}

// ---- pre-pass: X -> fp16 fragment-shuffled; block(0,0) also builds g_v2h ----
__global__ void __launch_bounds__(128) cvt_x_kernel(const float* __restrict__ x,
                                                    const float* __restrict__ v) {
    __shared__ float sm[16 * 128];
    const int tid = threadIdx.x;
    const int rb = blockIdx.y;
    const int c0 = blockIdx.x * 128;

    if (blockIdx.x == 0 && blockIdx.y == 0) {
        for (int i = tid; i < 8192; i += 128) {
            float a = (i < 8191) ? v[i] : 0.0f;
            float b = (i + 1 < 8191) ? v[i + 1] : 0.0f;
            __half2 h = __floats2half2_rn(a, b);
            g_v2h[i] = *reinterpret_cast<uint32_t*>(&h);
        }
    }
#pragma unroll
    for (int i = 0; i < 4; i++) {
        const int f = tid + 128 * i;
        const int r = f >> 5;
        const int cq = f & 31;
        float4 vv = *reinterpret_cast<const float4*>(
            x + (size_t)(rb * 16 + r) * K_DIM + c0 + cq * 4);
        float* s = sm + r * 128 + cq * 4;
        s[0] = vv.x; s[1] = vv.y; s[2] = vv.z; s[3] = vv.w;
    }
    __syncthreads();
#pragma unroll
    for (int i = 0; i < 4; i++) {
        const int p = tid + 128 * i;
        const int cbL = p >> 6;
        const int pw = p & 63;
        const int widx = pw * 2;
        const int lane = widx >> 2;
        const int j = widx & 3;
        const int g = lane >> 2;
        const int tig = lane & 3;
        const int k = cbL * 16 + 2 * tig + (j >> 1) * 8;
        __half2 lo = __floats2half2_rn(sm[g * 128 + k], sm[g * 128 + k + 1]);
        __half2 hi = __floats2half2_rn(sm[(g + 8) * 128 + k], sm[(g + 8) * 128 + k + 1]);
        uint2 u;
        u.x = *reinterpret_cast<uint32_t*>(&lo);
        u.y = *reinterpret_cast<uint32_t*>(&hi);
        *reinterpret_cast<uint2*>(
            g_xh + ((size_t)rb * 256 + (c0 >> 4) + cbL) * 128 + widx) = u;
    }
}

// Stage one iter's A tile for this warp: 8 cp.async.16 per lane.
__device__ __forceinline__ void issue_a(int u, uint32_t wstage,
                                        const uint32_t* g0, const uint32_t* g1,
                                        int lane) {
#pragma unroll
    for (int i = 0; i < 8; i++) {
        const int mm = i >> 2;
        const int ks = i & 3;
        const uint32_t* src = (mm ? g1 : g0) + (size_t)(4 * u + ks) * 128;
        cp16(wstage + i * 512 + lane * 16, src);
    }
}

__global__ void __launch_bounds__(THREADS, 2)
toeplitz_mma_kernel(float* __restrict__ out) {
    extern __shared__ char smem[];
    uint32_t* sv = reinterpret_cast<uint32_t*>(smem + SV_OFF);

    const int tid = threadIdx.x;
    const int wid = tid >> 5;
    const int lane = tid & 31;
    const int g = lane >> 2;
    const int tig = lane & 3;
    const int warpM = wid & 3;
    const int warpN = wid >> 2;

    const int n0 = blockIdx.x * BN;
    const int m0 = blockIdx.y * BM;
    const int vbase = 3968 - n0;

    // stage the whole vals pair-window once
    {
        const uint4* src = reinterpret_cast<const uint4*>(g_v2h + vbase);
        uint4* dst = reinterpret_cast<uint4*>(sv);
        for (int i = tid; i < VWIN_WORDS / 4; i += THREADS) dst[i] = src[i];
    }

    float acc[2][8][4];
#pragma unroll
    for (int mm = 0; mm < 2; mm++)
#pragma unroll
        for (int nn = 0; nn < 8; nn++)
#pragma unroll
            for (int r = 0; r < 4; r++) acc[mm][nn][r] = 0.0f;

    // per-warp A buffer bases
    const uint32_t swb = smem_u32(smem) + wid * (2 * WSTAGE_BYTES);
    const uint32_t* g0 = g_xh +
        ((size_t)((m0 >> 4) + warpM * 2 + 0) * 256) * 128 + lane * 4;
    const uint32_t* g1 = g_xh +
        ((size_t)((m0 >> 4) + warpM * 2 + 1) * 256) * 128 + lane * 4;

    // prologue: prefetch iters 0 and 1 (warp-private FIFO)
    issue_a(0, swb, g0, g1, lane);
    cp_commit();
    issue_a(1, swb + WSTAGE_BYTES, g0, g1, lane);
    cp_commit();

    __syncthreads();   // sv window ready; only CTA-wide barrier before epilogue

    const int Q = 2 * tig - g + 71 - warpN * 64;   // [0,77]

#pragma unroll 1
    for (int t = 0; t < NITER; t++) {
        cp_wait<1>();   // this warp's stage t data landed

        // 15 diagonal B fragments from smem window
        const uint32_t* vp = sv + 64 * t + Q;
        uint32_t Bf[15];
#pragma unroll
        for (int e = 0; e < 15; e++) Bf[e] = vp[8 * e];

        // A fragments: conflict-free LDS.128 from warp-private stage
        const char* wb = smem + wid * (2 * WSTAGE_BYTES) + (t & 1) * WSTAGE_BYTES;
        uint4 a0[4], a1[4];
#pragma unroll
        for (int ks = 0; ks < 4; ks++)
            a0[ks] = *reinterpret_cast<const uint4*>(wb + ks * 512 + lane * 16);
#pragma unroll
        for (int ks = 0; ks < 4; ks++)
            a1[ks] = *reinterpret_cast<const uint4*>(wb + (4 + ks) * 512 + lane * 16);

#pragma unroll
        for (int ks = 0; ks < 4; ks++)
#pragma unroll
            for (int nn = 0; nn < 8; nn++) {
                const int e = 2 * ks - nn + 7;
                mma_fp16(acc[0][nn], a0[ks].x, a0[ks].y, a0[ks].z, a0[ks].w,
                         Bf[e], Bf[e + 1]);
                mma_fp16(acc[1][nn], a1[ks].x, a1[ks].y, a1[ks].z, a1[ks].w,
                         Bf[e], Bf[e + 1]);
            }

        // refill the stage just consumed with iter t+2 (WAR-safe: its data was
        // register-latched before the MMAs above issued)
        if (t + 2 < NITER)
            issue_a(t + 2, swb + (t & 1) * WSTAGE_BYTES, g0, g1, lane);
        cp_commit();   // always commit to keep FIFO accounting uniform
    }

    // epilogue: c0/c1 adjacent columns -> float2 stores
#pragma unroll
    for (int mm = 0; mm < 2; mm++) {
        const int row = m0 + warpM * 32 + mm * 16 + g;
#pragma unroll
        for (int nn = 0; nn < 8; nn++) {
            const int col = n0 + warpN * 64 + nn * 8 + tig * 2;
            *reinterpret_cast<float2*>(out + (size_t)row * N_DIM + col) =
                make_float2(acc[mm][nn][0], acc[mm][nn][1]);
            *reinterpret_cast<float2*>(out + (size_t)(row + 8) * N_DIM + col) =
                make_float2(acc[mm][nn][2], acc[mm][nn][3]);
        }
    }
}

extern "C" void kernel_launch(void* const* d_in, const int* in_sizes, int n_in,
                              void* d_out, int out_size) {
    const float* x    = (const float*)d_in[0];
    const float* vals = (const float*)d_in[1];
    float* out        = (float*)d_out;

    static int attr_set = 0;
    if (!attr_set) {
        cudaFuncSetAttribute(toeplitz_mma_kernel,
                             cudaFuncAttributeMaxDynamicSharedMemorySize,
                             SMEM_TOTAL);
        attr_set = 1;
    }

    cvt_x_kernel<<<dim3(K_DIM / 128, M_DIM / 16), 128>>>(x, vals);

    dim3 grid(N_DIM / BN, M_DIM / BM);   // 32 x 64
    toeplitz_mma_kernel<<<grid, THREADS, SMEM_TOTAL>>>(out);
}

// round 13
// speedup vs baseline: 1.0496x; 1.0014x over previous
#include <cuda_runtime.h>
#include <cuda_fp16.h>
#include <cstdint>

// ToeplitzLinear: D[m,n] = sum_k X[m,k] * vals[4095 - n + k]
// R13 = R12 with a 3-stage warp-private cp.async ring (cp_wait<2> -> ~2 MMA
// iterations of L2-latency cover) and the refill issued between the two MMA
// half-blocks. Barrier-free mainloop, fragment-shuffled fp16 A scratch,
// CTA-lifetime vals pair-window in smem.

#define M_DIM 8192
#define N_DIM 4096
#define K_DIM 4096
#define BM 128
#define BN 128
#define BK 64
#define NITER (K_DIM / BK)       // 64
#define THREADS 256

#define VWIN_WORDS 4224
#define WSTAGE_BYTES 4096        // per warp per stage: 2 rb x 4 ks x 32 x 16B
#define NSTAGE 3
#define SV_OFF (8 * NSTAGE * WSTAGE_BYTES)          // 98304
#define SMEM_TOTAL (SV_OFF + VWIN_WORDS * 4)        // 115200 (x2 = 225KB/SM)

__device__ uint32_t g_xh[(size_t)M_DIM * K_DIM / 2];
__device__ uint32_t g_v2h[8192];   // g_v2h[i] = half2(w[i], w[i+1]), w = fp16(vals)

__device__ __forceinline__ uint32_t smem_u32(const void* p) {
    uint32_t a;
    asm("{ .reg .u64 t; cvta.to.shared.u64 t, %1; cvt.u32.u64 %0, t; }"
        : "=r"(a) : "l"(p));
    return a;
}
__device__ __forceinline__ void cp16(uint32_t saddr, const void* g) {
    asm volatile("cp.async.cg.shared.global [%0], [%1], 16;"
                 :: "r"(saddr), "l"(g) : "memory");
}
__device__ __forceinline__ void cp_commit() {
    asm volatile("cp.async.commit_group;" ::: "memory");
}
template <int N>
__device__ __forceinline__ void cp_wait() {
    asm volatile("cp.async.wait_group %0;" :: "n"(N) : "memory");
}
__device__ __forceinline__ void mma_fp16(float c[4], uint32_t a0, uint32_t a1,
                                         uint32_t a2, uint32_t a3,
                                         uint32_t b0, uint32_t b1) {
    asm volatile(
        "mma.sync.aligned.m16n8k16.row.col.f32.f16.f16.f32 "
        "{%0,%1,%2,%3}, {%4,%5,%6,%7}, {%8,%9}, {%0,%1,%2,%3};"
        : "+f"(c[0]), "+f"(c[1]), "+f"(c[2]), "+f"(c[3])
        : "r"(a0), "r"(a1), "r"(a2), "r"(a3), "r"(b0), "r"(b1));
}

// ---- pre-pass: X -> fp16 fragment-shuffled; block(0,0) also builds g_v2h ----
__global__ void __launch_bounds__(128) cvt_x_kernel(const float* __restrict__ x,
                                                    const float* __restrict__ v) {
    __shared__ float sm[16 * 128];
    const int tid = threadIdx.x;
    const int rb = blockIdx.y;
    const int c0 = blockIdx.x * 128;

    if (blockIdx.x == 0 && blockIdx.y == 0) {
        for (int i = tid; i < 8192; i += 128) {
            float a = (i < 8191) ? v[i] : 0.0f;
            float b = (i + 1 < 8191) ? v[i + 1] : 0.0f;
            __half2 h = __floats2half2_rn(a, b);
            g_v2h[i] = *reinterpret_cast<uint32_t*>(&h);
        }
    }
#pragma unroll
    for (int i = 0; i < 4; i++) {
        const int f = tid + 128 * i;
        const int r = f >> 5;
        const int cq = f & 31;
        float4 vv = *reinterpret_cast<const float4*>(
            x + (size_t)(rb * 16 + r) * K_DIM + c0 + cq * 4);
        float* s = sm + r * 128 + cq * 4;
        s[0] = vv.x; s[1] = vv.y; s[2] = vv.z; s[3] = vv.w;
    }
    __syncthreads();
#pragma unroll
    for (int i = 0; i < 4; i++) {
        const int p = tid + 128 * i;
        const int cbL = p >> 6;
        const int pw = p & 63;
        const int widx = pw * 2;
        const int lane = widx >> 2;
        const int j = widx & 3;
        const int g = lane >> 2;
        const int tig = lane & 3;
        const int k = cbL * 16 + 2 * tig + (j >> 1) * 8;
        __half2 lo = __floats2half2_rn(sm[g * 128 + k], sm[g * 128 + k + 1]);
        __half2 hi = __floats2half2_rn(sm[(g + 8) * 128 + k], sm[(g + 8) * 128 + k + 1]);
        uint2 u;
        u.x = *reinterpret_cast<uint32_t*>(&lo);
        u.y = *reinterpret_cast<uint32_t*>(&hi);
        *reinterpret_cast<uint2*>(
            g_xh + ((size_t)rb * 256 + (c0 >> 4) + cbL) * 128 + widx) = u;
    }
}

// Stage one iter's A tile for this warp: 8 cp.async.16 per lane.
__device__ __forceinline__ void issue_a(int u, uint32_t wstage,
                                        const uint32_t* g0, const uint32_t* g1,
                                        int lane) {
#pragma unroll
    for (int i = 0; i < 8; i++) {
        const int mm = i >> 2;
        const int ks = i & 3;
        const uint32_t* src = (mm ? g1 : g0) + (size_t)(4 * u + ks) * 128;
        cp16(wstage + i * 512 + lane * 16, src);
    }
}

__global__ void __launch_bounds__(THREADS, 2)
toeplitz_mma_kernel(float* __restrict__ out) {
    extern __shared__ char smem[];
    uint32_t* sv = reinterpret_cast<uint32_t*>(smem + SV_OFF);

    const int tid = threadIdx.x;
    const int wid = tid >> 5;
    const int lane = tid & 31;
    const int g = lane >> 2;
    const int tig = lane & 3;
    const int warpM = wid & 3;
    const int warpN = wid >> 2;

    const int n0 = blockIdx.x * BN;
    const int m0 = blockIdx.y * BM;
    const int vbase = 3968 - n0;

    // stage the whole vals pair-window once
    {
        const uint4* src = reinterpret_cast<const uint4*>(g_v2h + vbase);
        uint4* dst = reinterpret_cast<uint4*>(sv);
        for (int i = tid; i < VWIN_WORDS / 4; i += THREADS) dst[i] = src[i];
    }

    float acc[2][8][4];
#pragma unroll
    for (int mm = 0; mm < 2; mm++)
#pragma unroll
        for (int nn = 0; nn < 8; nn++)
#pragma unroll
            for (int r = 0; r < 4; r++) acc[mm][nn][r] = 0.0f;

    // per-warp A ring bases
    const uint32_t swb = smem_u32(smem) + wid * (NSTAGE * WSTAGE_BYTES);
    const uint32_t* g0 = g_xh +
        ((size_t)((m0 >> 4) + warpM * 2 + 0) * 256) * 128 + lane * 4;
    const uint32_t* g1 = g_xh +
        ((size_t)((m0 >> 4) + warpM * 2 + 1) * 256) * 128 + lane * 4;

    // prologue: prefetch iters 0..2 (warp-private FIFO)
    issue_a(0, swb, g0, g1, lane);
    cp_commit();
    issue_a(1, swb + WSTAGE_BYTES, g0, g1, lane);
    cp_commit();
    issue_a(2, swb + 2 * WSTAGE_BYTES, g0, g1, lane);
    cp_commit();

    __syncthreads();   // sv window ready; only CTA-wide barrier before epilogue

    const int Q = 2 * tig - g + 71 - warpN * 64;   // [0,77]

    int st = 0;        // stage index = t % 3, tracked incrementally
#pragma unroll 1
    for (int t = 0; t < NITER; t++) {
        cp_wait<2>();   // this warp's stage t landed (2 younger groups pending)

        // 15 diagonal B fragments from smem window
        const uint32_t* vp = sv + 64 * t + Q;
        uint32_t Bf[15];
#pragma unroll
        for (int e = 0; e < 15; e++) Bf[e] = vp[8 * e];

        // A fragments: conflict-free LDS.128 from warp-private stage
        const char* wb = smem + wid * (NSTAGE * WSTAGE_BYTES) + st * WSTAGE_BYTES;
        uint4 a0[4], a1[4];
#pragma unroll
        for (int ks = 0; ks < 4; ks++)
            a0[ks] = *reinterpret_cast<const uint4*>(wb + ks * 512 + lane * 16);
#pragma unroll
        for (int ks = 0; ks < 4; ks++)
            a1[ks] = *reinterpret_cast<const uint4*>(wb + (4 + ks) * 512 + lane * 16);

        // first MMA half (acc[0])
#pragma unroll
        for (int ks = 0; ks < 4; ks++)
#pragma unroll
            for (int nn = 0; nn < 8; nn++) {
                const int e = 2 * ks - nn + 7;
                mma_fp16(acc[0][nn], a0[ks].x, a0[ks].y, a0[ks].z, a0[ks].w,
                         Bf[e], Bf[e + 1]);
            }

        // refill consumed stage with iter t+3 (issues overlap tensor-busy time)
        if (t + 3 < NITER)
            issue_a(t + 3, swb + st * WSTAGE_BYTES, g0, g1, lane);
        cp_commit();   // always commit to keep FIFO accounting uniform

        // second MMA half (acc[1])
#pragma unroll
        for (int ks = 0; ks < 4; ks++)
#pragma unroll
            for (int nn = 0; nn < 8; nn++) {
                const int e = 2 * ks - nn + 7;
                mma_fp16(acc[1][nn], a1[ks].x, a1[ks].y, a1[ks].z, a1[ks].w,
                         Bf[e], Bf[e + 1]);
            }

        st = (st == NSTAGE - 1) ? 0 : st + 1;
    }

    // epilogue: c0/c1 adjacent columns -> float2 stores
#pragma unroll
    for (int mm = 0; mm < 2; mm++) {
        const int row = m0 + warpM * 32 + mm * 16 + g;
#pragma unroll
        for (int nn = 0; nn < 8; nn++) {
            const int col = n0 + warpN * 64 + nn * 8 + tig * 2;
            *reinterpret_cast<float2*>(out + (size_t)row * N_DIM + col) =
                make_float2(acc[mm][nn][0], acc[mm][nn][1]);
            *reinterpret_cast<float2*>(out + (size_t)(row + 8) * N_DIM + col) =
                make_float2(acc[mm][nn][2], acc[mm][nn][3]);
        }
    }
}

extern "C" void kernel_launch(void* const* d_in, const int* in_sizes, int n_in,
                              void* d_out, int out_size) {
    const float* x    = (const float*)d_in[0];
    const float* vals = (const float*)d_in[1];
    float* out        = (float*)d_out;

    static int attr_set = 0;
    if (!attr_set) {
        cudaFuncSetAttribute(toeplitz_mma_kernel,
                             cudaFuncAttributeMaxDynamicSharedMemorySize,
                             SMEM_TOTAL);
        attr_set = 1;
    }

    cvt_x_kernel<<<dim3(K_DIM / 128, M_DIM / 16), 128>>>(x, vals);

    dim3 grid(N_DIM / BN, M_DIM / BM);   // 32 x 64
    toeplitz_mma_kernel<<<grid, THREADS, SMEM_TOTAL>>>(out);
}

// round 14
// speedup vs baseline: 1.0667x; 1.0163x over previous
#include <cuda_runtime.h>
#include <cuda_fp16.h>
#include <cstdint>

// ToeplitzLinear: D[m,n] = sum_k X[m,k] * vals[4095 - n + k]
// R14: main = R12 (2-stage warp-private cp.async ring, barrier-free) with
// __stcs epilogue; prepass rebuilt conflict-free (132-float padded smem rows,
// LDS.128 fragment gather, uint4 stores).

#define M_DIM 8192
#define N_DIM 4096
#define K_DIM 4096
#define BM 128
#define BN 128
#define BK 64
#define NITER (K_DIM / BK)       // 64
#define THREADS 256

#define VWIN_WORDS 4224
#define WSTAGE_BYTES 4096        // per warp per stage: 2 rb x 4 ks x 32 x 16B
#define SV_OFF 65536             // 8 warps x 2 stages x 4KB
#define SMEM_TOTAL (SV_OFF + VWIN_WORDS * 4)   // 82432

__device__ uint32_t g_xh[(size_t)M_DIM * K_DIM / 2];
__device__ uint32_t g_v2h[8192];   // g_v2h[i] = half2(w[i], w[i+1]), w = fp16(vals)

__device__ __forceinline__ uint32_t smem_u32(const void* p) {
    uint32_t a;
    asm("{ .reg .u64 t; cvta.to.shared.u64 t, %1; cvt.u32.u64 %0, t; }"
        : "=r"(a) : "l"(p));
    return a;
}
__device__ __forceinline__ void cp16(uint32_t saddr, const void* g) {
    asm volatile("cp.async.cg.shared.global [%0], [%1], 16;"
                 :: "r"(saddr), "l"(g) : "memory");
}
__device__ __forceinline__ void cp_commit() {
    asm volatile("cp.async.commit_group;" ::: "memory");
}
template <int N>
__device__ __forceinline__ void cp_wait() {
    asm volatile("cp.async.wait_group %0;" :: "n"(N) : "memory");
}
__device__ __forceinline__ void mma_fp16(float c[4], uint32_t a0, uint32_t a1,
                                         uint32_t a2, uint32_t a3,
                                         uint32_t b0, uint32_t b1) {
    asm volatile(
        "mma.sync.aligned.m16n8k16.row.col.f32.f16.f16.f32 "
        "{%0,%1,%2,%3}, {%4,%5,%6,%7}, {%8,%9}, {%0,%1,%2,%3};"
        : "+f"(c[0]), "+f"(c[1]), "+f"(c[2]), "+f"(c[3])
        : "r"(a0), "r"(a1), "r"(a2), "r"(a3), "r"(b0), "r"(b1));
}
__device__ __forceinline__ uint32_t pack_h2(float a, float b) {
    __half2 h = __floats2half2_rn(a, b);
    return *reinterpret_cast<uint32_t*>(&h);
}

// ---- pre-pass: X -> fp16 fragment-shuffled (conflict-free) ----
// Block: 32 rows x 128 cols. Phase1: coalesced float4 -> padded smem (132/row).
// Phase2: each thread gathers 4 conflict-free LDS.128 and emits two complete
// fragment lanes as uint4. Block (0,0) also builds g_v2h.
#define PREROW 132
__global__ void __launch_bounds__(256) cvt_x_kernel(const float* __restrict__ x,
                                                    const float* __restrict__ v) {
    __shared__ float sm[32 * PREROW];
    const int tid = threadIdx.x;
    const int r0 = blockIdx.y * 32;       // 32-row block
    const int c0 = blockIdx.x * 128;      // 128-col chunk (8 cbs)

    if (blockIdx.x == 0 && blockIdx.y == 0) {
        for (int i = tid; i < 8192; i += 256) {
            float a = (i < 8191) ? v[i] : 0.0f;
            float b = (i + 1 < 8191) ? v[i + 1] : 0.0f;
            g_v2h[i] = pack_h2(a, b);
        }
    }
    // Phase 1: 1024 float4 chunks, 4 per thread
#pragma unroll
    for (int i = 0; i < 4; i++) {
        const int f = tid + 256 * i;      // 0..1023
        const int r = f >> 5;             // 0..31
        const int cq = f & 31;            // float4 col chunk
        float4 vv = *reinterpret_cast<const float4*>(
            x + (size_t)(r0 + r) * K_DIM + c0 + 4 * cq);
        *reinterpret_cast<float4*>(sm + r * PREROW + 4 * cq) = vv;
    }
    __syncthreads();

    // Phase 2: item p = tid: tile = p>>7 (16-row half), cb = (p>>4)&7,
    // g = p&7, h = (p>>3)&1  (quarter-warp = g 0..7, h fixed -> banks 4g+c ✓)
    {
        const int p = tid;
        const int tile = p >> 7;          // 0..1
        const int cb = (p >> 4) & 7;      // 0..7
        const int g = p & 7;
        const int h = (p >> 3) & 1;
        const float* base = sm + tile * 16 * PREROW + 16 * cb + 4 * h;
        float4 X0 = *reinterpret_cast<const float4*>(base + g * PREROW);
        float4 Y0 = *reinterpret_cast<const float4*>(base + (g + 8) * PREROW);
        float4 Z0 = *reinterpret_cast<const float4*>(base + g * PREROW + 8);
        float4 W0 = *reinterpret_cast<const float4*>(base + (g + 8) * PREROW + 8);

        const size_t rb = (size_t)(blockIdx.y * 2 + tile);
        const size_t cbg = (size_t)blockIdx.x * 8 + cb;
        uint32_t* dst = g_xh + (rb * 256 + cbg) * 128;

        const int l1 = g * 4 + 2 * h;     // tig = 2h
        uint4 u1;
        u1.x = pack_h2(X0.x, X0.y);
        u1.y = pack_h2(Y0.x, Y0.y);
        u1.z = pack_h2(Z0.x, Z0.y);
        u1.w = pack_h2(W0.x, W0.y);
        *reinterpret_cast<uint4*>(dst + l1 * 4) = u1;

        uint4 u2;                          // tig = 2h+1
        u2.x = pack_h2(X0.z, X0.w);
        u2.y = pack_h2(Y0.z, Y0.w);
        u2.z = pack_h2(Z0.z, Z0.w);
        u2.w = pack_h2(W0.z, W0.w);
        *reinterpret_cast<uint4*>(dst + (l1 + 1) * 4) = u2;
    }
}

// Stage one iter's A tile for this warp: 8 cp.async.16 per lane.
__device__ __forceinline__ void issue_a(int u, uint32_t wstage,
                                        const uint32_t* g0, const uint32_t* g1,
                                        int lane) {
#pragma unroll
    for (int i = 0; i < 8; i++) {
        const int mm = i >> 2;
        const int ks = i & 3;
        const uint32_t* src = (mm ? g1 : g0) + (size_t)(4 * u + ks) * 128;
        cp16(wstage + i * 512 + lane * 16, src);
    }
}

__global__ void __launch_bounds__(THREADS, 2)
toeplitz_mma_kernel(float* __restrict__ out) {
    extern __shared__ char smem[];
    uint32_t* sv = reinterpret_cast<uint32_t*>(smem + SV_OFF);

    const int tid = threadIdx.x;
    const int wid = tid >> 5;
    const int lane = tid & 31;
    const int g = lane >> 2;
    const int tig = lane & 3;
    const int warpM = wid & 3;
    const int warpN = wid >> 2;

    const int n0 = blockIdx.x * BN;
    const int m0 = blockIdx.y * BM;
    const int vbase = 3968 - n0;

    // stage the whole vals pair-window once
    {
        const uint4* src = reinterpret_cast<const uint4*>(g_v2h + vbase);
        uint4* dst = reinterpret_cast<uint4*>(sv);
        for (int i = tid; i < VWIN_WORDS / 4; i += THREADS) dst[i] = src[i];
    }

    float acc[2][8][4];
#pragma unroll
    for (int mm = 0; mm < 2; mm++)
#pragma unroll
        for (int nn = 0; nn < 8; nn++)
#pragma unroll
            for (int r = 0; r < 4; r++) acc[mm][nn][r] = 0.0f;

    const uint32_t swb = smem_u32(smem) + wid * (2 * WSTAGE_BYTES);
    const uint32_t* g0 = g_xh +
        ((size_t)((m0 >> 4) + warpM * 2 + 0) * 256) * 128 + lane * 4;
    const uint32_t* g1 = g_xh +
        ((size_t)((m0 >> 4) + warpM * 2 + 1) * 256) * 128 + lane * 4;

    issue_a(0, swb, g0, g1, lane);
    cp_commit();
    issue_a(1, swb + WSTAGE_BYTES, g0, g1, lane);
    cp_commit();

    __syncthreads();   // sv window ready; only CTA-wide barrier before epilogue

    const int Q = 2 * tig - g + 71 - warpN * 64;   // [0,77]

#pragma unroll 1
    for (int t = 0; t < NITER; t++) {
        cp_wait<1>();

        const uint32_t* vp = sv + 64 * t + Q;
        uint32_t Bf[15];
#pragma unroll
        for (int e = 0; e < 15; e++) Bf[e] = vp[8 * e];

        const char* wb = smem + wid * (2 * WSTAGE_BYTES) + (t & 1) * WSTAGE_BYTES;
        uint4 a0[4], a1[4];
#pragma unroll
        for (int ks = 0; ks < 4; ks++)
            a0[ks] = *reinterpret_cast<const uint4*>(wb + ks * 512 + lane * 16);
#pragma unroll
        for (int ks = 0; ks < 4; ks++)
            a1[ks] = *reinterpret_cast<const uint4*>(wb + (4 + ks) * 512 + lane * 16);

#pragma unroll
        for (int ks = 0; ks < 4; ks++)
#pragma unroll
            for (int nn = 0; nn < 8; nn++) {
                const int e = 2 * ks - nn + 7;
                mma_fp16(acc[0][nn], a0[ks].x, a0[ks].y, a0[ks].z, a0[ks].w,
                         Bf[e], Bf[e + 1]);
                mma_fp16(acc[1][nn], a1[ks].x, a1[ks].y, a1[ks].z, a1[ks].w,
                         Bf[e], Bf[e + 1]);
            }

        if (t + 2 < NITER)
            issue_a(t + 2, swb + (t & 1) * WSTAGE_BYTES, g0, g1, lane);
        cp_commit();
    }

    // epilogue: streaming stores (don't evict the L2-resident X scratch)
#pragma unroll
    for (int mm = 0; mm < 2; mm++) {
        const int row = m0 + warpM * 32 + mm * 16 + g;
#pragma unroll
        for (int nn = 0; nn < 8; nn++) {
            const int col = n0 + warpN * 64 + nn * 8 + tig * 2;
            __stcs(reinterpret_cast<float2*>(out + (size_t)row * N_DIM + col),
                   make_float2(acc[mm][nn][0], acc[mm][nn][1]));
            __stcs(reinterpret_cast<float2*>(out + (size_t)(row + 8) * N_DIM + col),
                   make_float2(acc[mm][nn][2], acc[mm][nn][3]));
        }
    }
}

extern "C" void kernel_launch(void* const* d_in, const int* in_sizes, int n_in,
                              void* d_out, int out_size) {
    const float* x    = (const float*)d_in[0];
    const float* vals = (const float*)d_in[1];
    float* out        = (float*)d_out;

    static int attr_set = 0;
    if (!attr_set) {
        cudaFuncSetAttribute(toeplitz_mma_kernel,
                             cudaFuncAttributeMaxDynamicSharedMemorySize,
                             SMEM_TOTAL);
        attr_set = 1;
    }

    cvt_x_kernel<<<dim3(K_DIM / 128, M_DIM / 32), 256>>>(x, vals);

    dim3 grid(N_DIM / BN, M_DIM / BM);   // 32 x 64
    toeplitz_mma_kernel<<<grid, THREADS, SMEM_TOTAL>>>(out);
}